// round 10
// baseline (speedup 1.0000x reference)
#include <cuda_runtime.h>
#include <cstdint>

// Sparse 3D conv via warp-level fp16 mma.sync (m16n8k16), single pass.
// R10: gather rows staged through a warp-private 4-stage cp.async ring with
// depth-3 cover (~3 iterations of latency hiding), NO shuffles (each lane
// loads its staged row's mask/idx directly), XOR-swizzled smem, 128-thread
// blocks at launch_bounds(128,7) for ~44% occupancy.

static constexpr int kMVox = 100000;
static constexpr int kKVol = 27;
static constexpr int kCIn  = 32;
static constexpr int kCOut = 64;
static constexpr int NW     = 4;       // warps per block
static constexpr int M_TILE = 64;      // 4 warps x 16 rows
static constexpr int STAGES = 4;

// B fragments, fp16, fragment-order with K-permutation:
// [koff][nb][lane] -> uint4 {ks0.b0, ks0.b1, ks1.b0, ks1.b1}
__device__ __align__(16) uint4 g_bfrag[kKVol * 8 * 32];

__device__ __forceinline__ unsigned f16x2(float x, float y) {
    unsigned r;
    asm("cvt.rn.f16x2.f32 %0, %1, %2;" : "=r"(r) : "f"(y), "f"(x));  // x -> low half
    return r;
}

__global__ void prep_kernel(const float* __restrict__ kw) {
    int koff = blockIdx.x, tid = threadIdx.x;       // 27 x 256
    int nb = tid >> 5, lane = tid & 31;
    int g = lane >> 2, t = lane & 3;
    int n = nb * 8 + g;
    const float* W = kw + koff * kCIn * kCOut;      // W[i][n]
    uint4 v;
    v.x = f16x2(W[(8 * t + 0) * kCOut + n], W[(8 * t + 1) * kCOut + n]);
    v.y = f16x2(W[(8 * t + 2) * kCOut + n], W[(8 * t + 3) * kCOut + n]);
    v.z = f16x2(W[(8 * t + 4) * kCOut + n], W[(8 * t + 5) * kCOut + n]);
    v.w = f16x2(W[(8 * t + 6) * kCOut + n], W[(8 * t + 7) * kCOut + n]);
    g_bfrag[(koff * 8 + nb) * 32 + lane] = v;
}

__device__ __forceinline__ void mma16816(float* d, const unsigned* a,
                                         unsigned b0, unsigned b1) {
    asm volatile(
        "mma.sync.aligned.m16n8k16.row.col.f32.f16.f16.f32 "
        "{%0,%1,%2,%3}, {%4,%5,%6,%7}, {%8,%9}, {%0,%1,%2,%3};"
        : "+f"(d[0]), "+f"(d[1]), "+f"(d[2]), "+f"(d[3])
        : "r"(a[0]), "r"(a[1]), "r"(a[2]), "r"(a[3]), "r"(b0), "r"(b1));
}

__device__ __forceinline__ float4 lds128(uint32_t addr) {
    float4 v;
    asm volatile("ld.shared.v4.f32 {%0,%1,%2,%3}, [%4];"
                 : "=f"(v.x), "=f"(v.y), "=f"(v.z), "=f"(v.w) : "r"(addr));
    return v;
}

__global__ __launch_bounds__(128, 7)
void conv_hmma_kernel(const float* __restrict__ feats,
                      const int*   __restrict__ in_idx,
                      const int*   __restrict__ mask,
                      float*       __restrict__ out) {
    __shared__ __align__(16) char stg[STAGES][NW][16 * 128];   // 32 KB
    const int w = threadIdx.x >> 5, lane = threadIdx.x & 31;
    const int g = lane >> 2, t = lane & 3;
    const int wbase = blockIdx.x * M_TILE + w * 16;
    // staging role: 2 lanes per row, each fills a 64B half-row
    const int row16 = lane >> 1, half = lane & 1;
    const int mrow = wbase + row16;
    const bool vrow = mrow < kMVox;

    const uint32_t smem0 = (uint32_t)__cvta_generic_to_shared(&stg[0][0][0]);
    const uint32_t wb = smem0 + w * 2048;

    // masked idx for this lane's staged row at offset k (direct, no shuffle)
    auto ldidx = [&](int k) -> int {
        size_t off = (size_t)k * kMVox;
        int mk = vrow ? mask[off + mrow] : 0;
        int ix = vrow ? in_idx[off + mrow] : 0;
        return (vrow && mk) ? ix : -1;
    };
    // issue cp.asyncs for stage s (no commit here)
    auto cp_body = [&](int s, int iv) {
        uint32_t sb = wb + (s & (STAGES - 1)) * (NW * 2048);
        const float* src = feats + (size_t)(iv < 0 ? 0 : iv) * kCIn + half * 16;
        int sz = (iv >= 0) ? 16 : 0;
#pragma unroll
        for (int j = 0; j < 4; ++j) {
            int c = half * 4 + j;
            uint32_t dst = sb + row16 * 128 + ((c ^ (row16 & 7)) << 4);
            asm volatile("cp.async.cg.shared.global [%0], [%1], 16, %2;"
                         :: "r"(dst), "l"(src + j * 4), "r"(sz));
        }
    };

    float acc[8][4];
#pragma unroll
    for (int i = 0; i < 8; ++i)
#pragma unroll
        for (int j = 0; j < 4; ++j) acc[i][j] = 0.f;

    // --- prologue: stage 0..2 committed, idx for stage 3 in flight ---
    cp_body(0, ldidx(0));
    asm volatile("cp.async.commit_group;" ::: "memory");
    cp_body(1, ldidx(1));
    asm volatile("cp.async.commit_group;" ::: "memory");
    cp_body(2, ldidx(2));
    asm volatile("cp.async.commit_group;" ::: "memory");
    int inext = ldidx(3);

    // swizzled read offsets (rows g, g+8; chunks 2t, 2t+1); (g+8)&7 == g&7
    const uint32_t oA0 = g * 128 + (((2 * t) ^ (g & 7)) << 4);
    const uint32_t oA1 = g * 128 + (((2 * t + 1) ^ (g & 7)) << 4);
    const uint32_t oB0 = (g + 8) * 128 + (((2 * t) ^ (g & 7)) << 4);
    const uint32_t oB1 = (g + 8) * 128 + (((2 * t + 1) ^ (g & 7)) << 4);

#pragma unroll 1
    for (int koff = 0; koff < kKVol; ++koff) {
        asm volatile("cp.async.wait_group 2;" ::: "memory");
        __syncwarp();
        const uint32_t sb = wb + (koff & (STAGES - 1)) * (NW * 2048);

        unsigned ak0[4], ak1[4];
        {
            float4 v = lds128(sb + oA0);
            ak0[0] = f16x2(v.x, v.y); ak0[2] = f16x2(v.z, v.w);
        }
        {
            float4 v = lds128(sb + oA1);
            ak1[0] = f16x2(v.x, v.y); ak1[2] = f16x2(v.z, v.w);
        }
        {
            float4 v = lds128(sb + oB0);
            ak0[1] = f16x2(v.x, v.y); ak0[3] = f16x2(v.z, v.w);
        }
        {
            float4 v = lds128(sb + oB1);
            ak1[1] = f16x2(v.x, v.y); ak1[3] = f16x2(v.z, v.w);
        }
        __syncwarp();   // all lanes done reading before any refill of this ring slot

        if (koff + 3 < kKVol) cp_body(koff + 3, inext);
        asm volatile("cp.async.commit_group;" ::: "memory");
        if (koff + 4 < kKVol) inext = ldidx(koff + 4);

        // --- MMA block: 8 n-blocks x 2 k-steps ---
        const uint4* bp = g_bfrag + (size_t)koff * 8 * 32 + lane;
#pragma unroll
        for (int nb = 0; nb < 8; ++nb) {
            uint4 bw = bp[nb * 32];
            mma16816(acc[nb], ak0, bw.x, bw.y);
            mma16816(acc[nb], ak1, bw.z, bw.w);
        }
    }

    // store: d0,d1 -> row wbase+g ; d2,d3 -> row wbase+g+8
    const int mA = wbase + g, mB = wbase + g + 8;
#pragma unroll
    for (int nb = 0; nb < 8; ++nb) {
        int n = nb * 8 + 2 * t;
        if (mA < kMVox)
            *(float2*)(out + (size_t)mA * kCOut + n) = make_float2(acc[nb][0], acc[nb][1]);
        if (mB < kMVox)
            *(float2*)(out + (size_t)mB * kCOut + n) = make_float2(acc[nb][2], acc[nb][3]);
    }
}

extern "C" void kernel_launch(void* const* d_in, const int* in_sizes, int n_in,
                              void* d_out, int out_size) {
    const float* feats  = (const float*)d_in[0];
    const float* kernel = (const float*)d_in[1];
    const int*   in_idx = (const int*)d_in[2];
    const int*   maskp  = (const int*)d_in[3];
    float*       out    = (float*)d_out;
    (void)in_sizes; (void)n_in; (void)out_size;

    prep_kernel<<<kKVol, 256>>>(kernel);
    int grid = (kMVox + M_TILE - 1) / M_TILE;   // 1563
    conv_hmma_kernel<<<grid, 128>>>(feats, in_idx, maskp, out);
}